// round 15
// baseline (speedup 1.0000x reference)
#include <cuda_runtime.h>
#include <math.h>
#include <limits.h>

// ---------------------------------------------------------------------------
// DictionaryMatchingTv — GB300 sm_103a
//   inputs: slice_signal [N*16] f32, db_mag [D*16] f32, db_t2s_s [D] f32,
//           db_b1s [D] f32, delta_t_r2p_ms [16] f32
//   output: [t2 (N) | b1 (N) | min_dist (N)] f32
//
// v14: 384 thr/block (3 warps/SMSP), 8 pixels/thread, 12-way dictionary
// split, 256 px/block, 144 blocks = one full wave. Atom pairs in f32x2
// lane0/lane1; signals packed per pixel-pair in BOTH orders (spp / sps) so
// each 80-B record feeds 16 atom-pixel scores with 64 fma2. Best tracked with
// fmaxf + per-chunk snapshots; index recovered by rescanning the winning
// chunk with IDENTICAL packed fma2 chains (bitwise reproducible). Split merge
// via shared memory (NSPLIT=12 does not divide the warp).
// score = dot - 0.5*d2; dist^2 = s2 - 2*score.
// ---------------------------------------------------------------------------

#define ETL     16
#define NSPLIT  12
#define NTHR    384
#define NPIX    8
#define CHN     8      // records per chunk (per thread)
#define MAXNP2  4096

__device__ float g_recs[MAXNP2 * 20];   // 80-B records: 16 vals + 2 bias + pad
__device__ float g_full[8192 * ETL];    // normalized atoms (generic fallback)
__device__ float g_d2[8192];            // ||atom||^2     (generic fallback)

// ---- f32x2 packed helpers (Blackwell-only PTX) -----------------------------
__device__ __forceinline__ unsigned long long pkf(float lo, float hi) {
    unsigned long long r;
    asm("mov.b64 %0, {%1, %2};" : "=l"(r) : "f"(lo), "f"(hi));
    return r;
}
__device__ __forceinline__ unsigned long long pku(unsigned lo, unsigned hi) {
    unsigned long long r;
    asm("mov.b64 %0, {%1, %2};" : "=l"(r) : "r"(lo), "r"(hi));
    return r;
}
__device__ __forceinline__ void unpk(float& lo, float& hi, unsigned long long v) {
    asm("mov.b64 {%0, %1}, %2;" : "=f"(lo), "=f"(hi) : "l"(v));
}
__device__ __forceinline__ void fma2(unsigned long long& d, unsigned long long a,
                                     unsigned long long b) {
    asm("fma.rn.f32x2 %0, %1, %2, %0;" : "+l"(d) : "l"(a), "l"(b));
}

// ---------------------------------------------------------------------------
// Kernel 1: normalize atoms, build 80-B pair records.
//   rec[2j+slot] = compacted SE value j of atom 2*pr+slot
//   rec[16+slot] = -0.5*d2   (pad atoms: -1e30, can never win)
// ---------------------------------------------------------------------------
__global__ void k_atoms(const float* __restrict__ db_mag,
                        const float* __restrict__ delta, int D, int NP2) {
    int a = blockIdx.x * blockDim.x + threadIdx.x;
    if (a >= NP2 * 2) return;

    int cols[ETL];
    int M = 0;
#pragma unroll
    for (int e = 0; e < ETL; e++) {
        if (delta[e] * 1e-3f < 1e-3f) cols[M++] = e;
    }

    int pr = a >> 1, slot = a & 1;
    float c[8];
#pragma unroll
    for (int j = 0; j < 8; j++) c[j] = 0.0f;
    float bias = -1e30f;  // pad sentinel

    if (a < D) {
        float w[ETL];
        float nn = 0.0f;
#pragma unroll
        for (int i = 0; i < ETL; i++) {
            float m = (delta[i] * 1e-3f < 1e-3f) ? 1.0f : 0.0f;
            float v = db_mag[a * ETL + i] * m;
            w[i] = v;
            nn += v * v;
        }
        nn = sqrtf(nn);
        float inv = (nn > 0.0f) ? 1.0f / nn : 0.0f;  // nan_to_num semantics
        float db[ETL];
        float d2 = 0.0f;
#pragma unroll
        for (int i = 0; i < ETL; i++) {
            db[i] = w[i] * inv;
            d2 += db[i] * db[i];
            g_full[a * ETL + i] = db[i];
        }
        g_d2[a] = d2;
        bias = -0.5f * d2;
        int mm = (M < 8) ? M : 8;
        for (int j = 0; j < mm; j++) c[j] = db[cols[j]];
    }

    float* rec = &g_recs[pr * 20];
#pragma unroll
    for (int j = 0; j < 8; j++) rec[j * 2 + slot] = c[j];
    rec[16 + slot] = bias;
    if (slot == 0) { rec[18] = 0.0f; rec[19] = 0.0f; }
}

// ---------------------------------------------------------------------------
// Kernel 2: match. 384 thr/block, 256 px/block, 8 px/thread, 12-way split.
// ---------------------------------------------------------------------------
__global__ void __launch_bounds__(NTHR, 1)
k_match(const float* __restrict__ sig, const float* __restrict__ t2s,
        const float* __restrict__ b1s, const float* __restrict__ delta,
        float* __restrict__ out, int N, int D, int NP2, int nchunks) {
    extern __shared__ float sm[];
    float* smBest = sm + NP2 * 20;                  // [NPIX][NTHR]
    int*   smIdx  = (int*)(smBest + NPIX * NTHR);   // [NPIX][NTHR]

    // ---- stage records to shared ----
    {
        const uint4* src = (const uint4*)g_recs;
        uint4* dst = (uint4*)sm;
        const int n4 = NP2 * 5;
        for (int i = threadIdx.x; i < n4; i += blockDim.x) dst[i] = src[i];
    }

    int cols[ETL];
    int M = 0;
#pragma unroll
    for (int e = 0; e < ETL; e++) {
        if (delta[e] * 1e-3f < 1e-3f) cols[M++] = e;
    }
    __syncthreads();

    const int tid = threadIdx.x;
    const int s = tid % NSPLIT;
    const int g = tid / NSPLIT;
    const int pixBase = blockIdx.x * 256 + g * NPIX;
    const bool fast = (M <= 8);

    // ---- per-pixel two-step normalize -> packed pixel-pair signals ----
    unsigned long long spp[4][8];  // (s_{2pp,j}, s_{2pp+1,j})
    unsigned long long sps[4][8];  // swapped order
    float s2[NPIX];
    {
        int mm = (M < 8) ? M : 8;
        float sv[NPIX][8];
#pragma unroll
        for (int k = 0; k < NPIX; k++) {
            int pix = pixBase + k;
            int n = (pix < N) ? pix : (N - 1);
            const float4* sp = (const float4*)(sig + (size_t)n * ETL);
            float4 f0 = sp[0], f1 = sp[1], f2 = sp[2], f3 = sp[3];
            float v[ETL] = {f0.x, f0.y, f0.z, f0.w, f1.x, f1.y, f1.z, f1.w,
                            f2.x, f2.y, f2.z, f2.w, f3.x, f3.y, f3.z, f3.w};
            float n1 = 0.0f;
#pragma unroll
            for (int i = 0; i < ETL; i++) n1 += v[i] * v[i];
            n1 = sqrtf(n1);
            float inv1 = (n1 > 0.0f) ? 1.0f / n1 : 0.0f;
            float w[8];
            float n2 = 0.0f;
#pragma unroll
            for (int j = 0; j < 8; j++) {
                float x = (fast && j < mm) ? v[cols[j]] * inv1 : 0.0f;
                w[j] = x;
                n2 += x * x;
            }
            n2 = sqrtf(n2);
            float inv2 = (n2 > 0.0f) ? 1.0f / n2 : 0.0f;
            float acc = 0.0f;
#pragma unroll
            for (int j = 0; j < 8; j++) {
                float q = w[j] * inv2;
                acc += q * q;
                sv[k][j] = q;
            }
            s2[k] = acc;
        }
#pragma unroll
        for (int pp = 0; pp < 4; pp++) {
#pragma unroll
            for (int j = 0; j < 8; j++) {
                spp[pp][j] = pkf(sv[2 * pp][j], sv[2 * pp + 1][j]);
                sps[pp][j] = pkf(sv[2 * pp + 1][j], sv[2 * pp][j]);
            }
        }
    }

    float best[NPIX];
    int idx[NPIX];
    int bc[NPIX];
#pragma unroll
    for (int k = 0; k < NPIX; k++) {
        best[k] = -INFINITY; idx[k] = INT_MAX; bc[k] = 0;
    }

    if (fast) {
#pragma unroll 1
        for (int c = 0; c < nchunks; c++) {
            float snap[NPIX];
#pragma unroll
            for (int k = 0; k < NPIX; k++) snap[k] = best[k];
            const int base = c * CHN;
#pragma unroll 2
            for (int i = 0; i < CHN; i++) {
                const int p = (base + i) * NSPLIT + s;
                const float* rec = sm + p * 20;
                uint4 qa = *(const uint4*)(rec);
                uint4 qb = *(const uint4*)(rec + 4);
                uint4 qc = *(const uint4*)(rec + 8);
                uint4 qd = *(const uint4*)(rec + 12);
                unsigned long long bias = *(const unsigned long long*)(rec + 16);
                unsigned long long u0 = pku(qa.x, qa.y), u1 = pku(qa.z, qa.w);
                unsigned long long u2 = pku(qb.x, qb.y), u3 = pku(qb.z, qb.w);
                unsigned long long u4 = pku(qc.x, qc.y), u5 = pku(qc.z, qc.w);
                unsigned long long u6 = pku(qd.x, qd.y), u7 = pku(qd.z, qd.w);
#pragma unroll
                for (int pp = 0; pp < 4; pp++) {
                    unsigned long long aA = bias, aB = bias;
                    fma2(aA, u0, spp[pp][0]); fma2(aB, u0, sps[pp][0]);
                    fma2(aA, u1, spp[pp][1]); fma2(aB, u1, sps[pp][1]);
                    fma2(aA, u2, spp[pp][2]); fma2(aB, u2, sps[pp][2]);
                    fma2(aA, u3, spp[pp][3]); fma2(aB, u3, sps[pp][3]);
                    fma2(aA, u4, spp[pp][4]); fma2(aB, u4, sps[pp][4]);
                    fma2(aA, u5, spp[pp][5]); fma2(aB, u5, sps[pp][5]);
                    fma2(aA, u6, spp[pp][6]); fma2(aB, u6, sps[pp][6]);
                    fma2(aA, u7, spp[pp][7]); fma2(aB, u7, sps[pp][7]);
                    float lo, hi;
                    // aA = (E·px_even, O·px_odd)
                    unpk(lo, hi, aA);
                    best[2 * pp]     = fmaxf(best[2 * pp],     lo);
                    best[2 * pp + 1] = fmaxf(best[2 * pp + 1], hi);
                    // aB = (E·px_odd, O·px_even)
                    unpk(lo, hi, aB);
                    best[2 * pp + 1] = fmaxf(best[2 * pp + 1], lo);
                    best[2 * pp]     = fmaxf(best[2 * pp],     hi);
                }
            }
#pragma unroll
            for (int k = 0; k < NPIX; k++)
                if (best[k] != snap[k]) bc[k] = c;
        }

        // ---- index recovery: rescan winning chunk with IDENTICAL chains ----
#pragma unroll
        for (int k = 0; k < NPIX; k++) {
            const float tgt = best[k];
            const int pp = k >> 1;
            const int odd = k & 1;
            int id = INT_MAX;
            const int base = bc[k] * CHN;
#pragma unroll 1
            for (int i = 0; i < CHN; i++) {
                const int p = (base + i) * NSPLIT + s;
                const float* rec = sm + p * 20;
                uint4 qa = *(const uint4*)(rec);
                uint4 qb = *(const uint4*)(rec + 4);
                uint4 qc = *(const uint4*)(rec + 8);
                uint4 qd = *(const uint4*)(rec + 12);
                unsigned long long bias = *(const unsigned long long*)(rec + 16);
                unsigned long long u0 = pku(qa.x, qa.y), u1 = pku(qa.z, qa.w);
                unsigned long long u2 = pku(qb.x, qb.y), u3 = pku(qb.z, qb.w);
                unsigned long long u4 = pku(qc.x, qc.y), u5 = pku(qc.z, qc.w);
                unsigned long long u6 = pku(qd.x, qd.y), u7 = pku(qd.z, qd.w);
                unsigned long long aA = bias, aB = bias;
                fma2(aA, u0, spp[pp][0]); fma2(aB, u0, sps[pp][0]);
                fma2(aA, u1, spp[pp][1]); fma2(aB, u1, sps[pp][1]);
                fma2(aA, u2, spp[pp][2]); fma2(aB, u2, sps[pp][2]);
                fma2(aA, u3, spp[pp][3]); fma2(aB, u3, sps[pp][3]);
                fma2(aA, u4, spp[pp][4]); fma2(aB, u4, sps[pp][4]);
                fma2(aA, u5, spp[pp][5]); fma2(aB, u5, sps[pp][5]);
                fma2(aA, u6, spp[pp][6]); fma2(aB, u6, sps[pp][6]);
                fma2(aA, u7, spp[pp][7]); fma2(aB, u7, sps[pp][7]);
                float loA, hiA, loB, hiB;
                unpk(loA, hiA, aA);
                unpk(loB, hiB, aB);
                // pixel k even: even-atom score = aA.lo, odd-atom = aB.hi
                // pixel k odd : even-atom score = aB.lo, odd-atom = aA.hi
                float se = odd ? loB : loA;
                float so = odd ? hiA : hiB;
                if (se == tgt) id = min(id, 2 * p);
                if (so == tgt) id = min(id, 2 * p + 1);
            }
            // cold safety net: full same-chain rescan with its own argmax
            if (id == INT_MAX) {
                float cb = -INFINITY;
#pragma unroll 1
                for (int p = s; p < NP2; p += NSPLIT) {
                    const float* rec = sm + p * 20;
                    uint4 qa = *(const uint4*)(rec);
                    uint4 qb = *(const uint4*)(rec + 4);
                    uint4 qc = *(const uint4*)(rec + 8);
                    uint4 qd = *(const uint4*)(rec + 12);
                    unsigned long long bias = *(const unsigned long long*)(rec + 16);
                    unsigned long long u0 = pku(qa.x, qa.y), u1 = pku(qa.z, qa.w);
                    unsigned long long u2 = pku(qb.x, qb.y), u3 = pku(qb.z, qb.w);
                    unsigned long long u4 = pku(qc.x, qc.y), u5 = pku(qc.z, qc.w);
                    unsigned long long u6 = pku(qd.x, qd.y), u7 = pku(qd.z, qd.w);
                    unsigned long long aA = bias, aB = bias;
                    fma2(aA, u0, spp[pp][0]); fma2(aB, u0, sps[pp][0]);
                    fma2(aA, u1, spp[pp][1]); fma2(aB, u1, sps[pp][1]);
                    fma2(aA, u2, spp[pp][2]); fma2(aB, u2, sps[pp][2]);
                    fma2(aA, u3, spp[pp][3]); fma2(aB, u3, sps[pp][3]);
                    fma2(aA, u4, spp[pp][4]); fma2(aB, u4, sps[pp][4]);
                    fma2(aA, u5, spp[pp][5]); fma2(aB, u5, sps[pp][5]);
                    fma2(aA, u6, spp[pp][6]); fma2(aB, u6, sps[pp][6]);
                    fma2(aA, u7, spp[pp][7]); fma2(aB, u7, sps[pp][7]);
                    float loA, hiA, loB, hiB;
                    unpk(loA, hiA, aA);
                    unpk(loB, hiB, aB);
                    float se = odd ? loB : loA;
                    float so = odd ? hiA : hiB;
                    if (se > cb) { cb = se; id = 2 * p; }
                    if (so > cb) { cb = so; id = 2 * p + 1; }
                }
                best[k] = cb;
            }
            idx[k] = id;
        }
    } else {
        // ---- generic fallback (any mask width): split 0 does full scan ----
        if (s == 0) {
#pragma unroll 1
            for (int k = 0; k < NPIX; k++) {
                int pix = pixBase + k;
                int n = (pix < N) ? pix : (N - 1);
                float sv[ETL];
                float n1 = 0.0f;
#pragma unroll
                for (int i = 0; i < ETL; i++) {
                    float x = sig[(size_t)n * ETL + i];
                    sv[i] = x;
                    n1 += x * x;
                }
                n1 = sqrtf(n1);
                float inv1 = (n1 > 0.0f) ? 1.0f / n1 : 0.0f;
                float n2 = 0.0f;
#pragma unroll
                for (int i = 0; i < ETL; i++) {
                    float m = (delta[i] * 1e-3f < 1e-3f) ? 1.0f : 0.0f;
                    sv[i] = sv[i] * inv1 * m;
                    n2 += sv[i] * sv[i];
                }
                n2 = sqrtf(n2);
                float inv2 = (n2 > 0.0f) ? 1.0f / n2 : 0.0f;
                float ss = 0.0f;
#pragma unroll
                for (int i = 0; i < ETL; i++) { sv[i] *= inv2; ss += sv[i] * sv[i]; }
                s2[k] = ss;
                float b = -INFINITY;
                int bi = 0;
                for (int d = 0; d < D; d++) {
                    float dot = 0.0f;
#pragma unroll
                    for (int i = 0; i < ETL; i++) dot += g_full[d * ETL + i] * sv[i];
                    float sc = dot - 0.5f * g_d2[d];
                    if (sc > b) { b = sc; bi = d; }
                }
                best[k] = b;
                idx[k] = bi;
            }
        }
    }

    // ---- merge the 12 splits via shared memory: max score, min index ----
    __syncthreads();  // all record reads done before reusing nothing; orders buf
#pragma unroll
    for (int k = 0; k < NPIX; k++) {
        smBest[k * NTHR + tid] = best[k];
        smIdx[k * NTHR + tid] = idx[k];
    }
    __syncthreads();

    if (s == 0) {
#pragma unroll 1
        for (int k = 0; k < NPIX; k++) {
            float b = best[k];
            int id = idx[k];
#pragma unroll
            for (int t = 1; t < NSPLIT; t++) {
                float ob = smBest[k * NTHR + tid + t];
                int oi = smIdx[k * NTHR + tid + t];
                if (ob > b || (ob == b && oi < id)) { b = ob; id = oi; }
            }
            int pix = pixBase + k;
            if (pix < N) {
                int a = id;
                if (a < 0 || a >= D) a = 0;  // safety (cannot trigger)
                float md = sqrtf(fmaxf(s2[k] - 2.0f * b, 0.0f));
                out[pix]         = t2s[a];
                out[N + pix]     = b1s[a];
                out[2 * N + pix] = md;
            }
        }
    }
}

// ---------------------------------------------------------------------------
extern "C" void kernel_launch(void* const* d_in, const int* in_sizes, int n_in,
                              void* d_out, int out_size) {
    const float* sig   = (const float*)d_in[0];
    const float* dbmag = (const float*)d_in[1];
    const float* t2s   = (const float*)d_in[2];
    const float* b1s   = (const float*)d_in[3];
    const float* delta = (const float*)d_in[4];

    const int D = in_sizes[2];                       // 4000
    const int N = in_sizes[0] / ETL;                 // 36864
    const int NP = (D + 1) / 2;                      // 2000 pairs
    const int Q  = (NP + NSPLIT - 1) / NSPLIT;       // 167 pairs/split
    const int nchunks = (Q + CHN - 1) / CHN;         // 21
    const int NP2 = nchunks * CHN * NSPLIT;          // 2016 padded pairs
    const size_t smem = (size_t)NP2 * 20 * sizeof(float)
                      + (size_t)NPIX * NTHR * sizeof(float)      // best buf
                      + (size_t)NPIX * NTHR * sizeof(int);       // idx buf
    // 161280 + 12288 + 12288 = 185856 B

    cudaFuncSetAttribute(k_match, cudaFuncAttributeMaxDynamicSharedMemorySize,
                         (int)smem);

    k_atoms<<<(NP2 * 2 + 127) / 128, 128>>>(dbmag, delta, D, NP2);
    int blocks = (N + 255) / 256;
    k_match<<<blocks, NTHR, smem>>>(sig, t2s, b1s, delta, (float*)d_out,
                                    N, D, NP2, nchunks);
}